// round 17
// baseline (speedup 1.0000x reference)
#include <cuda_runtime.h>
#include <cuda_bf16.h>
#include <cstdint>

// Problem constants
#define Bq   512
#define Tq   256
#define Fq   256
#define Hq   512
#define KTOT 768
#define NG   2048          // 4*Hq gate columns (reordered: col' = 4*j + gate)

// Tiling (mma.sync path — baseline PTX, no sm_100a features)
#define TM   64            // batch rows per CTA
#define TN   64            // gate cols per CTA (= 16 hidden units)
#define KC   64            // K elements per chunk
#define NKC  8             // step kernel: Hq / KC (x-part hoisted out)
#define NKCX 4             // gx kernel:   Fq / KC
#define NTH  256
#define RS   72            // smem row stride in bf16 (144 B, conflict-free ldmatrix)
#define NSTG 2             // pipeline stages (prefetch depth 1; 1 barrier/chunk)

// Smem stage layout (bytes): Ahi | Alo | Whi | Wlo
#define A_BYTES (TM * RS * 2)          // 9216
#define W_BYTES (TN * RS * 2)          // 9216
#define O_AHI 0
#define O_ALO (A_BYTES)
#define O_WHI (2 * A_BYTES)
#define O_WLO (2 * A_BYTES + W_BYTES)
#define STAGE_BYTES (2 * A_BYTES + 2 * W_BYTES)   // 36864
#define SMEM_BYTES (NSTG * STAGE_BYTES)           // 73728 (2 CTAs/SM: 144K < 227K)

// ---------------- persistent device state (no allocs allowed) ----------------
__device__ __nv_bfloat16 g_xhi[(size_t)Bq * Tq * Fq];
__device__ __nv_bfloat16 g_xlo[(size_t)Bq * Tq * Fq];
__device__ __nv_bfloat16 g_hhi[2][Bq * Hq];
__device__ __nv_bfloat16 g_hlo[2][Bq * Hq];
__device__ float         g_c[Bq * Hq];
__device__ __nv_bfloat16 g_Whi[NG * KTOT];   // reordered [col'][k]
__device__ __nv_bfloat16 g_Wlo[NG * KTOT];
__device__ float         g_br[NG];           // reordered combined bias
__device__ float         g_gx[(size_t)Tq * Bq * NG];   // precomputed x@Wih^T, [t][b][col']

// ---------------- helpers ----------------
__device__ __forceinline__ uint32_t smem_u32(const void* p) {
    uint32_t a;
    asm("{ .reg .u64 t; cvta.to.shared.u64 t, %1; cvt.u32.u64 %0, t; }" : "=r"(a) : "l"(p));
    return a;
}
#define CP16(dst, src) \
    asm volatile("cp.async.cg.shared.global [%0], [%1], 16;" :: "r"(dst), "l"(src) : "memory")
#define CP_COMMIT() asm volatile("cp.async.commit_group;" ::: "memory")
#define CP_WAIT0()  asm volatile("cp.async.wait_group 0;" ::: "memory")

__device__ __forceinline__ void ldsm4(uint32_t* r, uint32_t addr) {
    asm volatile("ldmatrix.sync.aligned.m8n8.x4.shared.b16 {%0,%1,%2,%3}, [%4];"
        : "=r"(r[0]), "=r"(r[1]), "=r"(r[2]), "=r"(r[3]) : "r"(addr));
}
__device__ __forceinline__ void mma16816(float* d, const uint32_t* a, const uint32_t* b) {
    asm volatile(
        "mma.sync.aligned.m16n8k16.row.col.f32.bf16.bf16.f32 "
        "{%0,%1,%2,%3}, {%4,%5,%6,%7}, {%8,%9}, {%0,%1,%2,%3};"
        : "+f"(d[0]), "+f"(d[1]), "+f"(d[2]), "+f"(d[3])
        : "r"(a[0]), "r"(a[1]), "r"(a[2]), "r"(a[3]), "r"(b[0]), "r"(b[1]));
}

__device__ __forceinline__ float fsig(float x)  { return 1.0f / (1.0f + __expf(-x)); }
__device__ __forceinline__ float ftanh(float x) { return 2.0f / (1.0f + __expf(-2.0f * x)) - 1.0f; }

// ---------------- prep kernels ----------------
__global__ void convert_x_kernel(const float* __restrict__ x) {
    size_t i = (size_t)blockIdx.x * blockDim.x + threadIdx.x;
    if (i >= (size_t)Bq * Tq * Fq) return;
    float v = x[i];
    __nv_bfloat16 hi = __float2bfloat16(v);
    g_xhi[i] = hi;
    g_xlo[i] = __float2bfloat16(v - __bfloat162float(hi));
}

__global__ void prep_w_kernel(const float* __restrict__ Wih, const float* __restrict__ Whh) {
    size_t i = (size_t)blockIdx.x * blockDim.x + threadIdx.x;
    if (i >= (size_t)NG * KTOT) return;
    int col = (int)(i / KTOT), k = (int)(i % KTOT);
    int r = (col & 3) * Hq + (col >> 2);            // original gate row (i,f,g,o blocks)
    float v = (k < Hq) ? Whh[(size_t)r * Hq + k] : Wih[(size_t)r * Fq + (k - Hq)];
    __nv_bfloat16 hi = __float2bfloat16(v);
    g_Whi[i] = hi;
    g_Wlo[i] = __float2bfloat16(v - __bfloat162float(hi));
}

__global__ void init_kernel(const float* __restrict__ bih, const float* __restrict__ bhh) {
    int i = blockIdx.x * blockDim.x + threadIdx.x;
    if (i < Bq * Hq) {
        g_hhi[0][i] = __float2bfloat16(0.0f);
        g_hlo[0][i] = __float2bfloat16(0.0f);
        g_c[i] = 0.0f;
    }
    if (i < NG) {
        int r = (i & 3) * Hq + (i >> 2);
        g_br[i] = bih[r] + bhh[r];
    }
}

// ---------------- x-precompute GEMM: G_x[t][b][col'] = x @ Wih^T (split bf16) ------------
// Grid (NG/TN, Bq*Tq/TM) = (32, 2048) = 65536 CTAs — oversubscribed (221 waves),
// so latency/barriers hide across CTAs (unlike the 1-wave step kernel).
__global__ __launch_bounds__(NTH, 2)
void gx_kernel()
{
    extern __shared__ char dyn_smem[];
    const uint32_t sb = smem_u32(dyn_smem);
    const int tid  = threadIdx.x;
    const int wid  = tid >> 5;
    const int lane = tid & 31;
    const int warpM = (wid & 1) * 32;
    const int warpN = (wid >> 1) * 16;

    const int bt0 = blockIdx.y * TM;   // 64 | 256 -> never straddles a batch boundary
    const int n0  = blockIdx.x * TN;

    float acc[2][2][4];
    #pragma unroll
    for (int mi = 0; mi < 2; mi++)
        #pragma unroll
        for (int nj = 0; nj < 2; nj++)
            #pragma unroll
            for (int r = 0; r < 4; r++) acc[mi][nj][r] = 0.0f;

    // loader: per tile 64 rows x 8 segs of 16B; 2 per thread
    auto load = [&](int c) {
        const int k0 = c * KC;
        const uint32_t stg = sb + (uint32_t)(c & (NSTG - 1)) * STAGE_BYTES;
        #pragma unroll
        for (int i = 0; i < 2; i++) {
            const int g = i * 256 + tid;
            const int row = g >> 3, seg = g & 7;
            const uint32_t d = (uint32_t)(row * (RS * 2) + seg * 16);
            const size_t ao = (size_t)(bt0 + row) * Fq + k0 + seg * 8;
            CP16(stg + O_AHI + d, g_xhi + ao);
            CP16(stg + O_ALO + d, g_xlo + ao);
            const size_t wo = (size_t)(n0 + row) * KTOT + Hq + k0 + seg * 8;
            CP16(stg + O_WHI + d, g_Whi + wo);
            CP16(stg + O_WLO + d, g_Wlo + wo);
        }
        CP_COMMIT();
    };

    load(0);
    const int aRowOff = (lane & 15) * RS + (lane >> 4) * 8;
    const int wRowOff = (((lane >> 4) & 1) * 8 + (lane & 7)) * RS + ((lane >> 3) & 1) * 8;

    for (int c = 0; c < NKCX; c++) {
        CP_WAIT0();
        __syncthreads();
        if (c + 1 < NKCX) load(c + 1);

        const uint32_t stg = sb + (uint32_t)(c & (NSTG - 1)) * STAGE_BYTES;
        #pragma unroll
        for (int kk = 0; kk < 4; kk++) {
            uint32_t ah[2][4], al[2][4], wh[4], wl[4];
            #pragma unroll
            for (int mi = 0; mi < 2; mi++) {
                const uint32_t off = (uint32_t)((warpM + mi * 16) * RS + kk * 16 + aRowOff) * 2;
                ldsm4(ah[mi], stg + O_AHI + off);
                ldsm4(al[mi], stg + O_ALO + off);
            }
            {
                const uint32_t off = (uint32_t)(warpN * RS + kk * 16 + wRowOff) * 2;
                ldsm4(wh, stg + O_WHI + off);
                ldsm4(wl, stg + O_WLO + off);
            }
            #pragma unroll
            for (int mi = 0; mi < 2; mi++)
                #pragma unroll
                for (int nj = 0; nj < 2; nj++)
                    mma16816(acc[mi][nj], ah[mi], &wh[nj * 2]);
            #pragma unroll
            for (int mi = 0; mi < 2; mi++)
                #pragma unroll
                for (int nj = 0; nj < 2; nj++)
                    mma16816(acc[mi][nj], al[mi], &wh[nj * 2]);
            #pragma unroll
            for (int mi = 0; mi < 2; mi++)
                #pragma unroll
                for (int nj = 0; nj < 2; nj++)
                    mma16816(acc[mi][nj], ah[mi], &wl[nj * 2]);
        }
    }

    // Store raw fragments: c0=(r,col), c1=(r,col+1), c2=(r+8,col), c3=(r+8,col+1).
    // A-row bt maps to x row b*Tq + t, so bt+8 = (b, t+8) (same b: row offset
    // within the 64-row tile is <= 63, tiles are 64-aligned, 256 | batch bound).
    // In g_gx[t][b][col'], (t+8, b) sits at base + 8*Bq*NG.
    #pragma unroll
    for (int mi = 0; mi < 2; mi++) {
        #pragma unroll
        for (int nj = 0; nj < 2; nj++) {
            const int bt  = bt0 + warpM + mi * 16 + (lane >> 2);
            const int col = n0 + warpN + nj * 8 + (lane & 3) * 2;
            const int b = bt >> 8, tt = bt & 255;   // Tq = 256
            float* base = g_gx + ((size_t)tt * Bq + b) * NG + col;
            *(float2*)base = make_float2(acc[mi][nj][0], acc[mi][nj][1]);
            *(float2*)(base + (size_t)8 * Bq * NG) = make_float2(acc[mi][nj][2], acc[mi][nj][3]);
        }
    }
}

// ---------------- step chunk loader (h only; K = Hq = 512) ----------------
__device__ __forceinline__ void load_chunk(
    int c, int m0, int n0, int tid, uint32_t sb,
    const __nv_bfloat16* __restrict__ hhi, const __nv_bfloat16* __restrict__ hlo)
{
    const int k0 = c * KC;
    const uint32_t stg = sb + (uint32_t)(c & (NSTG - 1)) * STAGE_BYTES;
    #pragma unroll
    for (int i = 0; i < 2; i++) {
        const int g = i * 256 + tid;
        const int row = g >> 3, seg = g & 7;
        const uint32_t d = (uint32_t)(row * (RS * 2) + seg * 16);
        const size_t ao = (size_t)(m0 + row) * Hq + k0 + seg * 8;
        CP16(stg + O_AHI + d, hhi + ao);
        CP16(stg + O_ALO + d, hlo + ao);
        const size_t wo = (size_t)(n0 + row) * KTOT + k0 + seg * 8;
        CP16(stg + O_WHI + d, g_Whi + wo);
        CP16(stg + O_WLO + d, g_Wlo + wo);
    }
    CP_COMMIT();
}

// ---------------- LSTM step: h-part GEMM (K=512) + G_x add + fused epilogue ----------------
// Grid (32, 8) = 256 CTAs, 2/SM. ONE barrier per chunk (see round-14 argument).
__global__ __launch_bounds__(NTH, 2)
void lstm_step_kernel(int t)
{
    extern __shared__ char dyn_smem[];
    const uint32_t sb = smem_u32(dyn_smem);
    const int tid  = threadIdx.x;
    const int wid  = tid >> 5;
    const int lane = tid & 31;
    const int warpM = (wid & 1) * 32;
    const int warpN = (wid >> 1) * 16;

    const int m0 = blockIdx.y * TM;
    const int n0 = blockIdx.x * TN;

    const __nv_bfloat16* __restrict__ hhi = g_hhi[t & 1];
    const __nv_bfloat16* __restrict__ hlo = g_hlo[t & 1];
    __nv_bfloat16* __restrict__ hhi_o = g_hhi[(t + 1) & 1];
    __nv_bfloat16* __restrict__ hlo_o = g_hlo[(t + 1) & 1];
    const float* __restrict__ gx = g_gx + (size_t)t * Bq * NG;

    float acc[2][2][4];
    #pragma unroll
    for (int mi = 0; mi < 2; mi++)
        #pragma unroll
        for (int nj = 0; nj < 2; nj++)
            #pragma unroll
            for (int r = 0; r < 4; r++) acc[mi][nj][r] = 0.0f;

    load_chunk(0, m0, n0, tid, sb, hhi, hlo);

    const int aRowOff = (lane & 15) * RS + (lane >> 4) * 8;
    const int wRowOff = (((lane >> 4) & 1) * 8 + (lane & 7)) * RS + ((lane >> 3) & 1) * 8;

    for (int c = 0; c < NKC; c++) {
        CP_WAIT0();
        __syncthreads();
        if (c + 1 < NKC) load_chunk(c + 1, m0, n0, tid, sb, hhi, hlo);

        const uint32_t stg = sb + (uint32_t)(c & (NSTG - 1)) * STAGE_BYTES;
        #pragma unroll
        for (int kk = 0; kk < 4; kk++) {
            uint32_t ah[2][4], al[2][4], wh[4], wl[4];
            #pragma unroll
            for (int mi = 0; mi < 2; mi++) {
                const uint32_t off = (uint32_t)((warpM + mi * 16) * RS + kk * 16 + aRowOff) * 2;
                ldsm4(ah[mi], stg + O_AHI + off);
                ldsm4(al[mi], stg + O_ALO + off);
            }
            {
                const uint32_t off = (uint32_t)(warpN * RS + kk * 16 + wRowOff) * 2;
                ldsm4(wh, stg + O_WHI + off);
                ldsm4(wl, stg + O_WLO + off);
            }
            #pragma unroll
            for (int mi = 0; mi < 2; mi++)
                #pragma unroll
                for (int nj = 0; nj < 2; nj++)
                    mma16816(acc[mi][nj], ah[mi], &wh[nj * 2]);
            #pragma unroll
            for (int mi = 0; mi < 2; mi++)
                #pragma unroll
                for (int nj = 0; nj < 2; nj++)
                    mma16816(acc[mi][nj], al[mi], &wh[nj * 2]);
            #pragma unroll
            for (int mi = 0; mi < 2; mi++)
                #pragma unroll
                for (int nj = 0; nj < 2; nj++)
                    mma16816(acc[mi][nj], ah[mi], &wl[nj * 2]);
        }
    }

    // ---- fused LSTM epilogue (gate exchange + G_x + bias + state update) ----
    const int q = lane & 3;
    #pragma unroll
    for (int mi = 0; mi < 2; mi++) {
        #pragma unroll
        for (int nj = 0; nj < 2; nj++) {
            float* cr = acc[mi][nj];
            const float e0 = __shfl_xor_sync(0xffffffffu, cr[0], 1);
            const float e1 = __shfl_xor_sync(0xffffffffu, cr[1], 1);
            const float e2 = __shfl_xor_sync(0xffffffffu, cr[2], 1);
            const float e3 = __shfl_xor_sync(0xffffffffu, cr[3], 1);
            const int nb = n0 + warpN + nj * 8 + (q >> 1) * 4;
            const float4 bb = *(const float4*)&g_br[nb];
            const int j = nb >> 2;
            float ri, rf, rg, ro;
            int m = m0 + warpM + mi * 16 + (lane >> 2);
            if ((lane & 1) == 0) { ri = cr[0]; rf = cr[1]; rg = e0;   ro = e1;   }
            else                 { ri = e2;    rf = e3;    rg = cr[2]; ro = cr[3]; m += 8; }
            const float4 gxv = *(const float4*)(gx + (size_t)m * NG + nb);
            const float ig = fsig (ri + bb.x + gxv.x);
            const float fg = fsig (rf + bb.y + gxv.y);
            const float gg = ftanh(rg + bb.z + gxv.z);
            const float og = fsig (ro + bb.w + gxv.w);
            const size_t idx = (size_t)m * Hq + j;
            const float cn = fg * g_c[idx] + ig * gg;
            g_c[idx] = cn;
            const float hv = og * ftanh(cn);
            const __nv_bfloat16 hh = __float2bfloat16(hv);
            hhi_o[idx] = hh;
            hlo_o[idx] = __float2bfloat16(hv - __bfloat162float(hh));
        }
    }
}

// out[b] = h_final[b,:] . W_out[0,:] + b_out[0]
__global__ void head_kernel(const float* __restrict__ Wout,
                            const float* __restrict__ bout,
                            float* __restrict__ out)
{
    const int b = blockIdx.x;
    const __nv_bfloat16* hi = g_hhi[0] + (size_t)b * Hq;   // T even -> final h in buffer 0
    const __nv_bfloat16* lo = g_hlo[0] + (size_t)b * Hq;
    float s = 0.0f;
    for (int k = threadIdx.x; k < Hq; k += blockDim.x)
        s += (__bfloat162float(hi[k]) + __bfloat162float(lo[k])) * Wout[k];
    __shared__ float red[32];
    #pragma unroll
    for (int o = 16; o; o >>= 1) s += __shfl_down_sync(0xffffffffu, s, o);
    if ((threadIdx.x & 31) == 0) red[threadIdx.x >> 5] = s;
    __syncthreads();
    if (threadIdx.x == 0)
        out[b] = red[0] + red[1] + red[2] + red[3] + bout[0];
}

extern "C" void kernel_launch(void* const* d_in, const int* in_sizes, int n_in,
                              void* d_out, int out_size)
{
    (void)in_sizes; (void)n_in; (void)out_size;
    const float* x    = (const float*)d_in[0];
    const float* Wih  = (const float*)d_in[1];
    const float* Whh  = (const float*)d_in[2];
    const float* bih  = (const float*)d_in[3];
    const float* bhh  = (const float*)d_in[4];
    const float* Wout = (const float*)d_in[5];
    const float* bout = (const float*)d_in[6];
    float* out = (float*)d_out;

    cudaFuncSetAttribute(lstm_step_kernel,
                         cudaFuncAttributeMaxDynamicSharedMemorySize, SMEM_BYTES);
    cudaFuncSetAttribute(gx_kernel,
                         cudaFuncAttributeMaxDynamicSharedMemorySize, SMEM_BYTES);

    {
        const size_t n = (size_t)Bq * Tq * Fq;
        convert_x_kernel<<<(unsigned)((n + 255) / 256), 256>>>(x);
    }
    {
        const size_t n = (size_t)NG * KTOT;
        prep_w_kernel<<<(unsigned)((n + 255) / 256), 256>>>(Wih, Whh);
    }
    init_kernel<<<(Bq * Hq + 255) / 256, 256>>>(bih, bhh);

    {
        dim3 ggrid(NG / TN, (Bq * Tq) / TM);   // (32, 2048)
        gx_kernel<<<ggrid, NTH, SMEM_BYTES>>>();
    }

    dim3 grid(NG / TN, Bq / TM);   // (32, 8) = 256 CTAs -> 2 per SM
    for (int t = 0; t < Tq; t++)
        lstm_step_kernel<<<grid, NTH, SMEM_BYTES>>>(t);

    head_kernel<<<Bq, 128>>>(Wout, bout, out);
}